// round 10
// baseline (speedup 1.0000x reference)
#include <cuda_runtime.h>
#include <cstdint>

// Problem constants
#define B_   4
#define N_   24
#define C_   256
#define H_   100
#define W_   100
#define OUT_ 7
#define P_   276                      // N*(N-1)/2
#define CH_  (C_ * OUT_ * OUT_)       // 12544 floats per full [C,7,7] chunk
#define HCH_ (CH_ / 2)                // 6272 floats per half-channel chunk
#define HW_  (H_ * W_)
#define SCALE_ 0.25f
#define NROIS_ (N_ + P_)              // 300 rois per batch
#define NV8_  (HCH_ / 8)              // 784 float8 per half tile

// NHWC scratch for features
__device__ float g_nhwc[(size_t)B_ * HW_ * C_];

// 256-bit global load (sm_100+): 8 floats, 32B aligned.
__device__ __forceinline__ void ldg256(const float* p, float* v) {
    asm volatile("ld.global.nc.v8.f32 {%0,%1,%2,%3,%4,%5,%6,%7}, [%8];"
                 : "=f"(v[0]), "=f"(v[1]), "=f"(v[2]), "=f"(v[3]),
                   "=f"(v[4]), "=f"(v[5]), "=f"(v[6]), "=f"(v[7])
                 : "l"(p));
}
// 256-bit streaming global store.
__device__ __forceinline__ void stcs256(float* p, const float* v) {
    asm volatile("st.global.cs.v8.f32 [%0], {%1,%2,%3,%4,%5,%6,%7,%8};"
                 :: "l"(p), "f"(v[0]), "f"(v[1]), "f"(v[2]), "f"(v[3]),
                    "f"(v[4]), "f"(v[5]), "f"(v[6]), "f"(v[7])
                 : "memory");
}

// ---------------------------------------------------------------------------
// Kernel 1: NCHW -> NHWC transpose, float4 stores.
// ---------------------------------------------------------------------------
__global__ void nchw_to_nhwc_kernel(const float* __restrict__ in) {
    __shared__ float tile[32][33];
    const int b   = blockIdx.z;
    const int c0  = blockIdx.y * 32;
    const int hw0 = blockIdx.x * 32;
    const int tx = threadIdx.x, ty = threadIdx.y;   // (32, 8)
    const int tid = ty * 32 + tx;

    const float* src = in + (size_t)b * C_ * HW_;
#pragma unroll
    for (int i = 0; i < 32; i += 8) {
        const int c  = c0 + ty + i;
        const int hw = hw0 + tx;
        float v = 0.0f;
        if (hw < HW_) v = src[(size_t)c * HW_ + hw];
        tile[ty + i][tx] = v;
    }
    __syncthreads();

    const int tx8 = tid & 7;     // float4 channel group
    const int tyy = tid >> 3;    // hw within tile
    const int hw  = hw0 + tyy;
    if (hw < HW_) {
        float4 v;
        v.x = tile[4 * tx8 + 0][tyy];
        v.y = tile[4 * tx8 + 1][tyy];
        v.z = tile[4 * tx8 + 2][tyy];
        v.w = tile[4 * tx8 + 3][tyy];
        float* dst = g_nhwc + (size_t)b * HW_ * C_;
        *reinterpret_cast<float4*>(&dst[(size_t)hw * C_ + c0 + 4 * tx8]) = v;
    }
}

// ---------------------------------------------------------------------------
// Kernel 2: TWO CTAs per roi (one per 128-channel half). 256 threads.
//  Phase B: 256-bit loads. Thread owns 8 channels (c8 = tid&15); 16 bin
//           slots with quad skew (conflict-free scalar STS, half-warp taps
//           contiguous 512B). 16 LDG.256 per bin (half the instructions of
//           the 128-bit version).
//  Phase C: stage half-tile into registers (float8 x4), then 256-bit
//           streaming-store fan-out.
// ---------------------------------------------------------------------------
__global__ __launch_bounds__(256, 4) void roi_pair_kernel(
    const float* __restrict__ boxes,   // [B, N, 4] xyxy, image coords
    float* __restrict__ out)           // [B*P, 3, C, 7, 7]
{
    __shared__ __align__(16) float pooled[HCH_];
    __shared__ int   sy0[14], sy1[14], sx0[14], sx1[14];
    __shared__ float sly[14], shy[14], slx[14], shx[14];

    const int bid  = blockIdx.x;
    const int tid  = threadIdx.x;
    const int r    = bid >> 1;       // roi id 0..1199 (objects first)
    const int half = bid & 1;        // channel half

    int b, m;  // batch, roi index within batch (m < N_: object, else union)
    if (r < B_ * N_) { b = r / N_; m = r % N_; }
    else { const int u = r - B_ * N_; b = u / P_; m = N_ + (u % P_); }

    // Separable sample tables: tid 0..13 -> x, 14..27 -> y.
    if (tid < 28) {
        float x1, y1, x2, y2;
        if (m < N_) {
            const float* bx = boxes + ((size_t)b * N_ + m) * 4;
            x1 = bx[0]; y1 = bx[1]; x2 = bx[2]; y2 = bx[3];
        } else {
            int p = m - N_;
            int i = 0, rem = p, cnt = N_ - 1;
            while (rem >= cnt) { rem -= cnt; ++i; --cnt; }
            const int j = i + 1 + rem;
            const float* ba = boxes + ((size_t)b * N_ + i) * 4;
            const float* bb = boxes + ((size_t)b * N_ + j) * 4;
            x1 = fminf(ba[0], bb[0]);
            y1 = fminf(ba[1], bb[1]);
            x2 = fmaxf(ba[2], bb[2]);
            y2 = fmaxf(ba[3], bb[3]);
        }
        const int  d   = tid % 14;
        const bool isY = (tid >= 14);
        const float c1 = (isY ? y1 : x1) * SCALE_;
        const float c2 = (isY ? y2 : x2) * SCALE_;
        const float sz  = fmaxf(c2 - c1, 1.0f);
        const float bsz = sz * (1.0f / OUT_);
        const float g = (float)(d >> 1) + ((float)(d & 1) + 0.5f) * 0.5f;
        const float X = c1 + g * bsz;
        const int   lim = isY ? H_ : W_;
        const bool  valid = (X > -1.0f) && (X < (float)lim);
        const float Xc  = fminf(fmaxf(X, 0.0f), (float)(lim - 1));
        const float x0f = floorf(Xc);
        float lx = Xc - x0f;
        float hx = 1.0f - lx;
        if (!valid) { lx = 0.0f; hx = 0.0f; }
        const int t0 = (int)x0f;
        const int t1 = min(t0 + 1, lim - 1);
        if (isY) { sy0[d] = t0; sy1[d] = t1; sly[d] = lx; shy[d] = hx; }
        else     { sx0[d] = t0; sx1[d] = t1; slx[d] = lx; shx[d] = hx; }
    }
    __syncthreads();

    // Phase B.
    const int c8   = tid & 15;          // 8-channel group 0..15 (128ch half)
    const int slot = tid >> 4;          // 0..15
    const int quad = (tid >> 2) & 3;    // 4-lane quad within warp
    const int res  = (slot + quad) & 15; // bin residue mod 16 (skewed)
    const float* __restrict__ featf =
        g_nhwc + (size_t)b * HW_ * C_ + half * (C_ / 2) + c8 * 8;

#pragma unroll 1
    for (int t = 0; t < 4; ++t) {
        const int bin = 16 * t + res;
        if (bin >= OUT_ * OUT_) break;
        const int py = bin / OUT_;
        const int px = bin - py * OUT_;
        float acc[8];
#pragma unroll
        for (int k = 0; k < 8; ++k) acc[k] = 0.0f;
#pragma unroll
        for (int sy = 0; sy < 2; ++sy) {
            const int   yi = 2 * py + sy;
            const int   y0 = sy0[yi], y1 = sy1[yi];
            const float ly = sly[yi], hy = shy[yi];
            const int r0 = y0 * W_;
            const int r1 = y1 * W_;
#pragma unroll
            for (int sx = 0; sx < 2; ++sx) {
                const int   xi = 2 * px + sx;
                const int   x0 = sx0[xi], x1 = sx1[xi];
                const float lx = slx[xi], hx = shx[xi];
                float f00[8], f01[8], f10[8], f11[8];
                ldg256(featf + (size_t)(r0 + x0) * C_, f00);
                ldg256(featf + (size_t)(r0 + x1) * C_, f01);
                ldg256(featf + (size_t)(r1 + x0) * C_, f10);
                ldg256(featf + (size_t)(r1 + x1) * C_, f11);
                const float w00 = hy * hx, w01 = hy * lx, w10 = ly * hx, w11 = ly * lx;
#pragma unroll
                for (int k = 0; k < 8; ++k)
                    acc[k] += w00 * f00[k] + w01 * f01[k] +
                              w10 * f10[k] + w11 * f11[k];
            }
        }
        // scalar STS x8; bank = 8*(c8&3) + 17*cc + res pattern verified
        // conflict-free across the warp for the quad-skewed res.
        const int base = (8 * c8) * 49 + bin;
#pragma unroll
        for (int k = 0; k < 8; ++k)
            pooled[base + 49 * k] = acc[k] * 0.25f;
    }
    __syncthreads();

    // Phase C: stage into registers once (LDS.128 x2 per float8), then
    // 256-bit streaming-store fan-out.
    float stage[4][8];
#pragma unroll
    for (int k = 0; k < 4; ++k) {
        const int idx = tid + k * 256;
        if (idx < NV8_) {
            const float4* s4 = reinterpret_cast<const float4*>(pooled) + idx * 2;
            float4 a = s4[0], c = s4[1];
            stage[k][0] = a.x; stage[k][1] = a.y; stage[k][2] = a.z; stage[k][3] = a.w;
            stage[k][4] = c.x; stage[k][5] = c.y; stage[k][6] = c.z; stage[k][7] = c.w;
        }
    }

    const int hoff = half * HCH_;   // float offset of this channel half
    if (m < N_) {
#pragma unroll 1
        for (int q = 0; q < N_ - 1; ++q) {
            int p, slot_o;
            const int hi = N_ - 1 - m;
            if (q < hi) {
                const int j = m + 1 + q;
                p = m * (N_ - 1) - (m * (m - 1)) / 2 + (j - m - 1);
                slot_o = 0;
            } else {
                const int i = q - hi;
                p = i * (N_ - 1) - (i * (i - 1)) / 2 + (m - i - 1);
                slot_o = 1;
            }
            float* dst = out + (((size_t)b * P_ + p) * 3 + slot_o) * CH_ + hoff;
#pragma unroll
            for (int k = 0; k < 4; ++k) {
                const int idx = tid + k * 256;
                if (idx < NV8_) stcs256(dst + idx * 8, stage[k]);
            }
        }
    } else {
        const int p = m - N_;
        float* dst = out + (((size_t)b * P_ + p) * 3 + 2) * CH_ + hoff;
#pragma unroll
        for (int k = 0; k < 4; ++k) {
            const int idx = tid + k * 256;
            if (idx < NV8_) stcs256(dst + idx * 8, stage[k]);
        }
    }
}

// ---------------------------------------------------------------------------
extern "C" void kernel_launch(void* const* d_in, const int* in_sizes, int n_in,
                              void* d_out, int out_size) {
    const float* features = (const float*)d_in[0];  // [B,C,H,W] float32
    const float* boxes    = (const float*)d_in[1];  // [B,N,4]   float32
    float* out = (float*)d_out;

    dim3 tgrid((HW_ + 31) / 32, C_ / 32, B_);
    nchw_to_nhwc_kernel<<<tgrid, dim3(32, 8)>>>(features);

    const int nblocks = 2 * B_ * NROIS_;   // 2400: 192 object CTAs first
    roi_pair_kernel<<<nblocks, 256>>>(boxes, out);
}